// round 11
// baseline (speedup 1.0000x reference)
#include <cuda_runtime.h>
#include <cuda_fp16.h>
#include <cuda_bf16.h>
#include <cstdint>

// int4 weight-only quantized GEMV on GB300.
// Logical: A [1, K=8192], B int32 [N, K/2] (one byte per int32, two nibbles,
// low nibble = even k), scalesAndZeros [N, K/32, 2], out [1, N].
// The harness transports fp16 tensors as float32 (exact upcast: low 13
// mantissa bits zero). We detect that signature at runtime and keep fp16/bf16
// fallbacks for robustness.

#define K_DIM   8192
#define KH      (K_DIM / 2)      // 4096 int32 words per row
#define NGROUP  (K_DIM / 32)     // 256 groups per row
#define WARPS   8
#define THREADS (WARPS * 32)
#define ITERS   (KH / (32 * 4))  // 32: each lane eats one uint4 (4 int32 = 8 weights) per iter

#define MODE_FP16 0
#define MODE_FP32 1
#define MODE_BF16 2

__device__ int g_mode;

// Dtype probe over the first 4096 32-bit words of A.
//  FP32-from-fp16 signature: every word has low 13 mantissa bits == 0
//  (fp16->fp32 upcast is exact; fp16 mantissa occupies fp32 bits 13-22).
//  Genuine fp16 or bf16 data packs two values per word; the low half's
//  mantissa bits land in bits 0-12 and are ~never all-zero for all 4096 words.
//  fp16 vs bf16: max |halfword as fp16|. fp16 N(0,1) max ~4.1 (>3.0 w.h.p.);
//  bf16 bits reinterpreted as fp16 are bounded ~2.3. Threshold 3.0 (0x4200).
__global__ void probe_kernel(const uint32_t* __restrict__ A)
{
    __shared__ int lo13_nonzero;
    __shared__ int maxmag;
    if (threadIdx.x == 0) { lo13_nonzero = 0; maxmag = 0; }
    __syncthreads();

    int nz = 0, lmax = 0;
    for (int i = threadIdx.x; i < 4096; i += THREADS) {
        uint32_t w = A[i];
        if (w & 0x1FFFu) nz++;
        int m0 = (int)(w & 0x7FFFu);
        int m1 = (int)((w >> 16) & 0x7FFFu);
        lmax = max(lmax, max(m0, m1));
    }
    if (nz) atomicAdd(&lo13_nonzero, nz);
    atomicMax(&maxmag, lmax);
    __syncthreads();

    if (threadIdx.x == 0) {
        if (lo13_nonzero == 0)      g_mode = MODE_FP32;  // exact-upcast signature
        else if (maxmag > 0x4200)   g_mode = MODE_FP16;
        else                        g_mode = MODE_BF16;
    }
}

__global__ __launch_bounds__(THREADS)
void gemv_int4_kernel(const void* __restrict__ Aptr,
                      const int*  __restrict__ B,
                      const void* __restrict__ SZptr,
                      void*       __restrict__ outptr,
                      int N)
{
    const int mode = g_mode;

    // A staged as 4096 packed half2 pairs (a[2j], a[2j+1]) = 16 KB.
    // fp32->fp16 / bf16->fp16 conversions are exact for fp16-origin data.
    __shared__ __align__(16) uint32_t a_sm[KH];

    if (mode == MODE_FP32) {
        const float2* Av = reinterpret_cast<const float2*>(Aptr);
        for (int i = threadIdx.x; i < KH; i += THREADS) {
            float2 v = Av[i];
            half2 h = __floats2half2_rn(v.x, v.y);
            a_sm[i] = *reinterpret_cast<uint32_t*>(&h);
        }
    } else if (mode == MODE_BF16) {
        const uint32_t* Av = reinterpret_cast<const uint32_t*>(Aptr);
        for (int i = threadIdx.x; i < KH; i += THREADS) {
            uint32_t w = Av[i];
            uint32_t lo = w << 16, hi = w & 0xFFFF0000u;  // bf16 -> fp32 is a shift
            half2 h = __floats2half2_rn(__uint_as_float(lo), __uint_as_float(hi));
            a_sm[i] = *reinterpret_cast<uint32_t*>(&h);
        }
    } else { // MODE_FP16
        const uint4* Av = reinterpret_cast<const uint4*>(Aptr);
        uint4* As = reinterpret_cast<uint4*>(a_sm);
        for (int i = threadIdx.x; i < KH / 4; i += THREADS)
            As[i] = Av[i];
    }
    __syncthreads();

    const int warp = threadIdx.x >> 5;
    const int lane = threadIdx.x & 31;
    const int n = blockIdx.x * WARPS + warp;
    if (n >= N) return;

    const uint4* Brow = reinterpret_cast<const uint4*>(B + (size_t)n * KH); // 1024 uint4

    const half2 c1032 = __halves2half2(__ushort_as_half(0x6408), __ushort_as_half(0x6408)); // 1032.0

    float2 facc = make_float2(0.f, 0.f);

    #pragma unroll 8
    for (int it = 0; it < ITERS; ++it) {
        const int idx = it * 32 + lane;        // uint4 index within row; covers k [idx*8, idx*8+8)
        uint4 bv = __ldcs(&Brow[idx]);         // streaming: 4 int32 = 8 int4 weights

        // one (scale, zero) per 8 weights; group = idx >> 2 (8 weights never straddle a group)
        half2 s2, z2;
        if (mode == MODE_FP32) {
            float2 szf = reinterpret_cast<const float2*>(SZptr)[(size_t)n * NGROUP + (idx >> 2)];
            s2 = __half2half2(__float2half_rn(szf.x));  // exact for fp16-origin data
            z2 = __half2half2(__float2half_rn(szf.y));
        } else if (mode == MODE_BF16) {
            uint32_t w = reinterpret_cast<const uint32_t*>(SZptr)[(size_t)n * NGROUP + (idx >> 2)];
            uint32_t lo = w << 16, hi = w & 0xFFFF0000u;
            s2 = __half2half2(__float2half_rn(__uint_as_float(lo)));
            z2 = __half2half2(__float2half_rn(__uint_as_float(hi)));
        } else {
            uint32_t szv = reinterpret_cast<const uint32_t*>(SZptr)[(size_t)n * NGROUP + (idx >> 2)];
            half2 szh = *reinterpret_cast<half2*>(&szv);
            s2 = __half2half2(__low2half(szh));
            z2 = __half2half2(__high2half(szh));
        }

        // matching activation pairs from smem: 4 consecutive half2
        uint4 av = *reinterpret_cast<const uint4*>(&a_sm[idx * 4]);

        half2 acc2;
        {
            uint32_t v, hbits; half2 h2, d2, w2, a2;

            v = (uint32_t)bv.x;
            hbits = ((v & 0xFu) | 0x64006400u) | ((v << 12) & 0x000F0000u);
            h2 = *reinterpret_cast<half2*>(&hbits);
            d2 = __hsub2(h2, c1032);           // exact: (q - 8) as half2 (Sterbenz)
            w2 = __hfma2(d2, s2, z2);
            a2 = *reinterpret_cast<half2*>(&av.x);
            acc2 = __hmul2(a2, w2);

            v = (uint32_t)bv.y;
            hbits = ((v & 0xFu) | 0x64006400u) | ((v << 12) & 0x000F0000u);
            h2 = *reinterpret_cast<half2*>(&hbits);
            d2 = __hsub2(h2, c1032);
            w2 = __hfma2(d2, s2, z2);
            a2 = *reinterpret_cast<half2*>(&av.y);
            acc2 = __hfma2(a2, w2, acc2);

            v = (uint32_t)bv.z;
            hbits = ((v & 0xFu) | 0x64006400u) | ((v << 12) & 0x000F0000u);
            h2 = *reinterpret_cast<half2*>(&hbits);
            d2 = __hsub2(h2, c1032);
            w2 = __hfma2(d2, s2, z2);
            a2 = *reinterpret_cast<half2*>(&av.z);
            acc2 = __hfma2(a2, w2, acc2);

            v = (uint32_t)bv.w;
            hbits = ((v & 0xFu) | 0x64006400u) | ((v << 12) & 0x000F0000u);
            h2 = *reinterpret_cast<half2*>(&hbits);
            d2 = __hsub2(h2, c1032);
            w2 = __hfma2(d2, s2, z2);
            a2 = *reinterpret_cast<half2*>(&av.w);
            acc2 = __hfma2(a2, w2, acc2);
        }

        // flush 4-term half2 chain to fp32
        float2 f = __half22float2(acc2);
        facc.x += f.x;
        facc.y += f.y;
    }

    float sum = facc.x + facc.y;
    #pragma unroll
    for (int off = 16; off > 0; off >>= 1)
        sum += __shfl_xor_sync(0xFFFFFFFFu, sum, off);

    if (lane == 0) {
        if (mode == MODE_FP32)
            reinterpret_cast<float*>(outptr)[n] = sum;
        else if (mode == MODE_BF16)
            reinterpret_cast<__nv_bfloat16*>(outptr)[n] = __float2bfloat16(sum);
        else
            reinterpret_cast<__half*>(outptr)[n] = __float2half(sum);
    }
}

extern "C" void kernel_launch(void* const* d_in, const int* in_sizes, int n_in,
                              void* d_out, int out_size)
{
    // Identify tensors by element count (ordering-proof):
    //   A = 8192, B = 67,108,864 (N*K/2), SZ = 8,388,608 (N*K/32*2)
    int iA = -1, iB = -1, iS = -1;
    for (int i = 0; i < n_in; ++i) {
        if      (in_sizes[i] == K_DIM) iA = i;
        else if (iB < 0 || in_sizes[i] > in_sizes[iB]) { if (iB >= 0) iS = iB; iB = i; }
        else iS = i;
    }
    // iB = largest non-A tensor (B), iS = the remaining one (SZ)
    if (iA < 0 || iB < 0 || iS < 0) { iA = 0; iB = 1; iS = 2; }

    const void* A  = d_in[iA];
    const int*  B  = (const int*)d_in[iB];
    const void* SZ = d_in[iS];

    const int N = in_sizes[iB] / KH;

    probe_kernel<<<1, THREADS>>>((const uint32_t*)A);

    const int grid = (N + WARPS - 1) / WARPS;
    gemv_int4_kernel<<<grid, THREADS>>>(A, B, SZ, d_out, N);
}

// round 13
// speedup vs baseline: 1.0261x; 1.0261x over previous
#include <cuda_runtime.h>
#include <cuda_fp16.h>
#include <cuda_bf16.h>
#include <cstdint>

// int4 weight-only quantized GEMV on GB300.
// Logical: A [1, K=8192], B int32 [N, K/2] (one byte per int32, two nibbles,
// low nibble = even k), scalesAndZeros [N, K/32, 2], out [1, N].
// The harness transports fp16 tensors as float32 (exact upcast, low 13
// mantissa bits zero) — detected at runtime; fp16/bf16 fallbacks kept.

#define K_DIM   8192
#define KH      (K_DIM / 2)      // 4096 int32 words per row
#define NGROUP  (K_DIM / 32)     // 256 groups per row
#define WARPS   8
#define THREADS (WARPS * 32)
#define ROWS    2                // N-rows per warp
#define GPL     (NGROUP / 32)    // 8 groups per lane

#define MODE_FP16 0
#define MODE_FP32 1
#define MODE_BF16 2

__device__ int g_mode;

// Dtype probe over the first 4096 32-bit words of A.
// FP32-from-fp16 signature: low 13 mantissa bits of every word are zero.
// Genuine fp16/bf16 data (two values/word) has random bits 0-12.
// fp16 vs bf16: max |halfword as fp16| (fp16 N(0,1) max ~4.1; bf16 bits as
// fp16 bounded ~2.3; threshold 3.0 = 0x4200).
__global__ void probe_kernel(const uint32_t* __restrict__ A)
{
    __shared__ int lo13_nonzero;
    __shared__ int maxmag;
    if (threadIdx.x == 0) { lo13_nonzero = 0; maxmag = 0; }
    __syncthreads();

    int nz = 0, lmax = 0;
    for (int i = threadIdx.x; i < 4096; i += THREADS) {
        uint32_t w = A[i];
        if (w & 0x1FFFu) nz++;
        int m0 = (int)(w & 0x7FFFu);
        int m1 = (int)((w >> 16) & 0x7FFFu);
        lmax = max(lmax, max(m0, m1));
    }
    if (nz) atomicAdd(&lo13_nonzero, nz);
    atomicMax(&maxmag, lmax);
    __syncthreads();

    if (threadIdx.x == 0) {
        if (lo13_nonzero == 0)      g_mode = MODE_FP32;
        else if (maxmag > 0x4200)   g_mode = MODE_FP16;
        else                        g_mode = MODE_BF16;
    }
}

// A staged in smem as half2 pairs, uint4-granular with +25% padding so the
// 64B-strided group reads are bank-conflict-free:
//   logical uint4 index i = 4*g + j  ->  physical uint4 index 5*g + j
#define A_SM_WORDS (5120)

__device__ __forceinline__ int a_phys32(int idx32) {
    int i4 = idx32 >> 2;
    return (i4 + (i4 >> 2)) * 4 + (idx32 & 3);
}

template<int MODE>
__device__ __forceinline__ void load_sz(const void* __restrict__ SZ, size_t row, int g,
                                        half2& s2, half2& z2)
{
    if (MODE == MODE_FP32) {
        float2 f = __ldcs(&reinterpret_cast<const float2*>(SZ)[row * NGROUP + g]);
        s2 = __half2half2(__float2half_rn(f.x));   // exact for fp16-origin data
        z2 = __half2half2(__float2half_rn(f.y));
    } else if (MODE == MODE_BF16) {
        uint32_t w = __ldcs(&reinterpret_cast<const uint32_t*>(SZ)[row * NGROUP + g]);
        uint32_t lo = w << 16, hi = w & 0xFFFF0000u;
        s2 = __half2half2(__float2half_rn(__uint_as_float(lo)));
        z2 = __half2half2(__float2half_rn(__uint_as_float(hi)));
    } else {
        uint32_t w = __ldcs(&reinterpret_cast<const uint32_t*>(SZ)[row * NGROUP + g]);
        half2 szh = *reinterpret_cast<half2*>(&w);
        s2 = __half2half2(__low2half(szh));
        z2 = __half2half2(__high2half(szh));
    }
}

// 4 half2 dequant+dot chain for one uint4 (8 weights), flushed to fp32.
__device__ __forceinline__ void dot_u4(uint4 bv, uint4 av, half2 s2, half2 z2,
                                       half2 c1032, float2& facc)
{
    uint32_t v, hb; half2 h2, d2, w2, a2, acc2;

    v = (uint32_t)bv.x;
    hb = ((v & 0xFu) | 0x64006400u) | ((v << 12) & 0x000F0000u);
    h2 = *reinterpret_cast<half2*>(&hb);
    d2 = __hsub2(h2, c1032);                 // exact (q - 8), Sterbenz
    w2 = __hfma2(d2, s2, z2);
    a2 = *reinterpret_cast<half2*>(&av.x);
    acc2 = __hmul2(a2, w2);

    v = (uint32_t)bv.y;
    hb = ((v & 0xFu) | 0x64006400u) | ((v << 12) & 0x000F0000u);
    h2 = *reinterpret_cast<half2*>(&hb);
    d2 = __hsub2(h2, c1032);
    w2 = __hfma2(d2, s2, z2);
    a2 = *reinterpret_cast<half2*>(&av.y);
    acc2 = __hfma2(a2, w2, acc2);

    v = (uint32_t)bv.z;
    hb = ((v & 0xFu) | 0x64006400u) | ((v << 12) & 0x000F0000u);
    h2 = *reinterpret_cast<half2*>(&hb);
    d2 = __hsub2(h2, c1032);
    w2 = __hfma2(d2, s2, z2);
    a2 = *reinterpret_cast<half2*>(&av.z);
    acc2 = __hfma2(a2, w2, acc2);

    v = (uint32_t)bv.w;
    hb = ((v & 0xFu) | 0x64006400u) | ((v << 12) & 0x000F0000u);
    h2 = *reinterpret_cast<half2*>(&hb);
    d2 = __hsub2(h2, c1032);
    w2 = __hfma2(d2, s2, z2);
    a2 = *reinterpret_cast<half2*>(&av.w);
    acc2 = __hfma2(a2, w2, acc2);

    float2 f = __half22float2(acc2);
    facc.x += f.x;
    facc.y += f.y;
}

// Double-buffered mainloop: lane processes one 32-weight group per stage for
// two N-rows; next stage's 8 uint4 + 2 scale pairs prefetched into registers
// before computing the current stage (true MLP ~= 8 LDG.128 per warp).
template<int MODE>
__device__ __forceinline__ void mainloop(const uint4* __restrict__ B0,
                                         const uint4* __restrict__ B1,
                                         const void* __restrict__ SZ, size_t n0,
                                         const uint4* __restrict__ As4, int lane,
                                         float2& f0, float2& f1)
{
    const half2 c1032 = __half2half2(__ushort_as_half(0x6408));  // 1032.0

    int g = lane;
    uint4 cb0[4], cb1[4];
    half2 cs0, cz0, cs1, cz1;

    load_sz<MODE>(SZ, n0,     g, cs0, cz0);
    load_sz<MODE>(SZ, n0 + 1, g, cs1, cz1);
    #pragma unroll
    for (int j = 0; j < 4; ++j) {
        cb0[j] = __ldcs(&B0[g * 4 + j]);
        cb1[j] = __ldcs(&B1[g * 4 + j]);
    }

    #pragma unroll
    for (int sup = 0; sup < GPL; ++sup) {
        uint4 nb0[4], nb1[4];
        half2 ns0, nz0, ns1, nz1;
        const int gn = g + 32;
        if (sup + 1 < GPL) {
            load_sz<MODE>(SZ, n0,     gn, ns0, nz0);
            load_sz<MODE>(SZ, n0 + 1, gn, ns1, nz1);
            #pragma unroll
            for (int j = 0; j < 4; ++j) {
                nb0[j] = __ldcs(&B0[gn * 4 + j]);
                nb1[j] = __ldcs(&B1[gn * 4 + j]);
            }
        }

        #pragma unroll
        for (int j = 0; j < 4; ++j) {
            uint4 av = As4[g * 5 + j];          // padded layout: conflict-free
            dot_u4(cb0[j], av, cs0, cz0, c1032, f0);
            dot_u4(cb1[j], av, cs1, cz1, c1032, f1);
        }

        if (sup + 1 < GPL) {
            #pragma unroll
            for (int j = 0; j < 4; ++j) { cb0[j] = nb0[j]; cb1[j] = nb1[j]; }
            cs0 = ns0; cz0 = nz0; cs1 = ns1; cz1 = nz1;
            g = gn;
        }
    }
}

__global__ __launch_bounds__(THREADS)
void gemv_int4_kernel(const void* __restrict__ Aptr,
                      const int*  __restrict__ B,
                      const void* __restrict__ SZptr,
                      void*       __restrict__ outptr,
                      int N)
{
    const int mode = g_mode;

    __shared__ __align__(16) uint32_t a_sm[A_SM_WORDS];

    if (mode == MODE_FP32) {
        const float2* Av = reinterpret_cast<const float2*>(Aptr);
        for (int i = threadIdx.x; i < KH; i += THREADS) {
            float2 v = Av[i];
            half2 h = __floats2half2_rn(v.x, v.y);
            a_sm[a_phys32(i)] = *reinterpret_cast<uint32_t*>(&h);
        }
    } else if (mode == MODE_BF16) {
        const uint32_t* Av = reinterpret_cast<const uint32_t*>(Aptr);
        for (int i = threadIdx.x; i < KH; i += THREADS) {
            uint32_t w = Av[i];
            uint32_t lo = w << 16, hi = w & 0xFFFF0000u;   // bf16 -> fp32 shift
            half2 h = __floats2half2_rn(__uint_as_float(lo), __uint_as_float(hi));
            a_sm[a_phys32(i)] = *reinterpret_cast<uint32_t*>(&h);
        }
    } else { // MODE_FP16
        const uint32_t* Av = reinterpret_cast<const uint32_t*>(Aptr);
        for (int i = threadIdx.x; i < KH; i += THREADS)
            a_sm[a_phys32(i)] = Av[i];
    }
    __syncthreads();

    const int warp = threadIdx.x >> 5;
    const int lane = threadIdx.x & 31;
    const int n0 = (blockIdx.x * WARPS + warp) * ROWS;
    if (n0 + 1 >= N + 1) return;   // grid sized exactly; guard kept for safety
    if (n0 >= N) return;

    const uint4* B0  = reinterpret_cast<const uint4*>(B + (size_t)n0 * KH);
    const uint4* B1  = reinterpret_cast<const uint4*>(B + (size_t)(n0 + 1) * KH);
    const uint4* As4 = reinterpret_cast<const uint4*>(a_sm);

    float2 f0 = make_float2(0.f, 0.f);
    float2 f1 = make_float2(0.f, 0.f);

    if (mode == MODE_FP32)
        mainloop<MODE_FP32>(B0, B1, SZptr, (size_t)n0, As4, lane, f0, f1);
    else if (mode == MODE_BF16)
        mainloop<MODE_BF16>(B0, B1, SZptr, (size_t)n0, As4, lane, f0, f1);
    else
        mainloop<MODE_FP16>(B0, B1, SZptr, (size_t)n0, As4, lane, f0, f1);

    float s0 = f0.x + f0.y;
    float s1 = f1.x + f1.y;
    #pragma unroll
    for (int off = 16; off > 0; off >>= 1) {
        s0 += __shfl_xor_sync(0xFFFFFFFFu, s0, off);
        s1 += __shfl_xor_sync(0xFFFFFFFFu, s1, off);
    }

    if (lane == 0) {
        if (mode == MODE_FP32) {
            reinterpret_cast<float*>(outptr)[n0]     = s0;
            reinterpret_cast<float*>(outptr)[n0 + 1] = s1;
        } else if (mode == MODE_BF16) {
            reinterpret_cast<__nv_bfloat16*>(outptr)[n0]     = __float2bfloat16(s0);
            reinterpret_cast<__nv_bfloat16*>(outptr)[n0 + 1] = __float2bfloat16(s1);
        } else {
            reinterpret_cast<__half*>(outptr)[n0]     = __float2half(s0);
            reinterpret_cast<__half*>(outptr)[n0 + 1] = __float2half(s1);
        }
    }
}

extern "C" void kernel_launch(void* const* d_in, const int* in_sizes, int n_in,
                              void* d_out, int out_size)
{
    // Identify tensors by element count (ordering-proof):
    //   A = 8192, B = N*K/2 (largest), SZ = N*K/32*2
    int iA = -1, iB = -1, iS = -1;
    for (int i = 0; i < n_in; ++i) {
        if      (in_sizes[i] == K_DIM) iA = i;
        else if (iB < 0 || in_sizes[i] > in_sizes[iB]) { if (iB >= 0) iS = iB; iB = i; }
        else iS = i;
    }
    if (iA < 0 || iB < 0 || iS < 0) { iA = 0; iB = 1; iS = 2; }

    const void* A  = d_in[iA];
    const int*  B  = (const int*)d_in[iB];
    const void* SZ = d_in[iS];

    const int N = in_sizes[iB] / KH;

    probe_kernel<<<1, THREADS>>>((const uint32_t*)A);

    const int rows_per_block = WARPS * ROWS;
    const int grid = (N + rows_per_block - 1) / rows_per_block;
    gemv_int4_kernel<<<grid, THREADS>>>(A, B, SZ, d_out, N);
}

// round 14
// speedup vs baseline: 1.2522x; 1.2203x over previous
#include <cuda_runtime.h>
#include <cuda_fp16.h>
#include <cuda_bf16.h>
#include <cstdint>

// int4 weight-only quantized GEMV on GB300.
// Logical: A [1, K=8192], B int32 [N, K/2] (one byte per int32, two nibbles,
// low nibble = even k), scalesAndZeros [N, K/32, 2], out [1, N].
// The harness transports fp16 tensors as float32 (exact upcast, low 13
// mantissa bits zero) — detected at runtime; fp16/bf16 fallbacks kept.

#define K_DIM   8192
#define KH      (K_DIM / 2)      // 4096 int32 words per row
#define NGROUP  (K_DIM / 32)     // 256 groups per row
#define WARPS   8
#define THREADS (WARPS * 32)
#define ROWS    4                // N-rows per warp
#define GPL     (NGROUP / 32)    // 8 stages: one group per lane per stage

#define MODE_FP16 0
#define MODE_FP32 1
#define MODE_BF16 2

__device__ int g_mode;

// Dtype probe over the first 4096 32-bit words of A.
// FP32-from-fp16 signature: low 13 mantissa bits of every word are zero.
// Genuine fp16/bf16 data (two values/word) has random bits 0-12.
// fp16 vs bf16 fallback: max |halfword as fp16| (fp16 N(0,1) max ~4.1;
// bf16 bits as fp16 bounded ~2.3; threshold 3.0 = 0x4200).
__global__ void probe_kernel(const uint32_t* __restrict__ A)
{
    __shared__ int lo13_nonzero;
    __shared__ int maxmag;
    if (threadIdx.x == 0) { lo13_nonzero = 0; maxmag = 0; }
    __syncthreads();

    int nz = 0, lmax = 0;
    for (int i = threadIdx.x; i < 4096; i += THREADS) {
        uint32_t w = A[i];
        if (w & 0x1FFFu) nz++;
        int m0 = (int)(w & 0x7FFFu);
        int m1 = (int)((w >> 16) & 0x7FFFu);
        lmax = max(lmax, max(m0, m1));
    }
    if (nz) atomicAdd(&lo13_nonzero, nz);
    atomicMax(&maxmag, lmax);
    __syncthreads();

    if (threadIdx.x == 0) {
        if (lo13_nonzero == 0)      g_mode = MODE_FP32;
        else if (maxmag > 0x4200)   g_mode = MODE_FP16;
        else                        g_mode = MODE_BF16;
    }
}

// A staged in smem as half2 pairs, uint4-granular with +25% padding so the
// 64B-strided group reads are bank-conflict-free:
//   logical uint4 index i4 = 4*g + j  ->  physical uint4 index 5*g + j
#define A_SM_WORDS (5120)

__device__ __forceinline__ int a_phys32(int idx32) {
    int i4 = idx32 >> 2;
    return (i4 + (i4 >> 2)) * 4 + (idx32 & 3);
}

template<int MODE>
__device__ __forceinline__ void load_sz(const void* __restrict__ SZ, size_t row, int g,
                                        half2& s2, half2& z2)
{
    if (MODE == MODE_FP32) {
        float2 f = __ldcs(&reinterpret_cast<const float2*>(SZ)[row * NGROUP + g]);
        s2 = __half2half2(__float2half_rn(f.x));   // exact for fp16-origin data
        z2 = __half2half2(__float2half_rn(f.y));
    } else if (MODE == MODE_BF16) {
        uint32_t w = __ldcs(&reinterpret_cast<const uint32_t*>(SZ)[row * NGROUP + g]);
        uint32_t lo = w << 16, hi = w & 0xFFFF0000u;
        s2 = __half2half2(__float2half_rn(__uint_as_float(lo)));
        z2 = __half2half2(__float2half_rn(__uint_as_float(hi)));
    } else {
        uint32_t w = __ldcs(&reinterpret_cast<const uint32_t*>(SZ)[row * NGROUP + g]);
        half2 szh = *reinterpret_cast<half2*>(&w);
        s2 = __half2half2(__low2half(szh));
        z2 = __half2half2(__high2half(szh));
    }
}

// 4 half2 dequant+dot chain for one uint4 (8 weights), flushed to fp32.
__device__ __forceinline__ void dot_u4(uint4 bv, uint4 av, half2 s2, half2 z2,
                                       half2 c1032, float2& facc)
{
    uint32_t v, hb; half2 h2, d2, w2, a2, acc2;

    v = (uint32_t)bv.x;
    hb = ((v & 0xFu) | 0x64006400u) | ((v << 12) & 0x000F0000u);
    h2 = *reinterpret_cast<half2*>(&hb);
    d2 = __hsub2(h2, c1032);                 // exact (q - 8), Sterbenz
    w2 = __hfma2(d2, s2, z2);
    a2 = *reinterpret_cast<half2*>(&av.x);
    acc2 = __hmul2(a2, w2);

    v = (uint32_t)bv.y;
    hb = ((v & 0xFu) | 0x64006400u) | ((v << 12) & 0x000F0000u);
    h2 = *reinterpret_cast<half2*>(&hb);
    d2 = __hsub2(h2, c1032);
    w2 = __hfma2(d2, s2, z2);
    a2 = *reinterpret_cast<half2*>(&av.y);
    acc2 = __hfma2(a2, w2, acc2);

    v = (uint32_t)bv.z;
    hb = ((v & 0xFu) | 0x64006400u) | ((v << 12) & 0x000F0000u);
    h2 = *reinterpret_cast<half2*>(&hb);
    d2 = __hsub2(h2, c1032);
    w2 = __hfma2(d2, s2, z2);
    a2 = *reinterpret_cast<half2*>(&av.z);
    acc2 = __hfma2(a2, w2, acc2);

    v = (uint32_t)bv.w;
    hb = ((v & 0xFu) | 0x64006400u) | ((v << 12) & 0x000F0000u);
    h2 = *reinterpret_cast<half2*>(&hb);
    d2 = __hsub2(h2, c1032);
    w2 = __hfma2(d2, s2, z2);
    a2 = *reinterpret_cast<half2*>(&av.w);
    acc2 = __hfma2(a2, w2, acc2);

    float2 f = __half22float2(acc2);
    facc.x += f.x;
    facc.y += f.y;
}

// Front-batched mainloop: per stage, each lane owns one 32-weight quant group
// (g = stage*32 + lane) across FOUR consecutive N-rows. All 16 uint4 B loads
// + 4 scale loads are issued before any compute consumes them — the
// same-iteration dependence makes the MLP scheduler-proof.
template<int MODE>
__device__ __forceinline__ void mainloop(const uint4* __restrict__ Br[ROWS],
                                         const void* __restrict__ SZ, size_t n0,
                                         const uint4* __restrict__ As4, int lane,
                                         float2* facc)
{
    const half2 c1032 = __half2half2(__ushort_as_half(0x6408));  // 1032.0

    #pragma unroll
    for (int sup = 0; sup < GPL; ++sup) {
        const int g = sup * 32 + lane;

        uint4 bv[ROWS][4];
        half2 s2[ROWS], z2[ROWS];

        // ---- issue all loads first (16 LDG.128 + 4 LDG.64) ----
        #pragma unroll
        for (int r = 0; r < ROWS; ++r) {
            #pragma unroll
            for (int j = 0; j < 4; ++j)
                bv[r][j] = __ldcs(&Br[r][g * 4 + j]);
        }
        #pragma unroll
        for (int r = 0; r < ROWS; ++r)
            load_sz<MODE>(SZ, n0 + r, g, s2[r], z2[r]);

        // ---- compute: one smem av read serves all 4 rows ----
        #pragma unroll
        for (int j = 0; j < 4; ++j) {
            uint4 av = As4[g * 5 + j];          // padded layout: conflict-free
            #pragma unroll
            for (int r = 0; r < ROWS; ++r)
                dot_u4(bv[r][j], av, s2[r], z2[r], c1032, facc[r]);
        }
    }
}

__global__ __launch_bounds__(THREADS, 2)
void gemv_int4_kernel(const void* __restrict__ Aptr,
                      const int*  __restrict__ B,
                      const void* __restrict__ SZptr,
                      void*       __restrict__ outptr,
                      int N)
{
    const int mode = g_mode;

    __shared__ __align__(16) uint32_t a_sm[A_SM_WORDS];

    if (mode == MODE_FP32) {
        const float2* Av = reinterpret_cast<const float2*>(Aptr);
        for (int i = threadIdx.x; i < KH; i += THREADS) {
            float2 v = Av[i];
            half2 h = __floats2half2_rn(v.x, v.y);
            a_sm[a_phys32(i)] = *reinterpret_cast<uint32_t*>(&h);
        }
    } else if (mode == MODE_BF16) {
        const uint32_t* Av = reinterpret_cast<const uint32_t*>(Aptr);
        for (int i = threadIdx.x; i < KH; i += THREADS) {
            uint32_t w = Av[i];
            uint32_t lo = w << 16, hi = w & 0xFFFF0000u;   // bf16 -> fp32 shift
            half2 h = __floats2half2_rn(__uint_as_float(lo), __uint_as_float(hi));
            a_sm[a_phys32(i)] = *reinterpret_cast<uint32_t*>(&h);
        }
    } else { // MODE_FP16
        const uint32_t* Av = reinterpret_cast<const uint32_t*>(Aptr);
        for (int i = threadIdx.x; i < KH; i += THREADS)
            a_sm[a_phys32(i)] = Av[i];
    }
    __syncthreads();

    const int warp = threadIdx.x >> 5;
    const int lane = threadIdx.x & 31;
    const int n0 = (blockIdx.x * WARPS + warp) * ROWS;
    if (n0 >= N) return;

    const uint4* Br[ROWS];
    #pragma unroll
    for (int r = 0; r < ROWS; ++r)
        Br[r] = reinterpret_cast<const uint4*>(B + (size_t)(n0 + r) * KH);
    const uint4* As4 = reinterpret_cast<const uint4*>(a_sm);

    float2 facc[ROWS];
    #pragma unroll
    for (int r = 0; r < ROWS; ++r) facc[r] = make_float2(0.f, 0.f);

    if (mode == MODE_FP32)
        mainloop<MODE_FP32>(Br, SZptr, (size_t)n0, As4, lane, facc);
    else if (mode == MODE_BF16)
        mainloop<MODE_BF16>(Br, SZptr, (size_t)n0, As4, lane, facc);
    else
        mainloop<MODE_FP16>(Br, SZptr, (size_t)n0, As4, lane, facc);

    float s[ROWS];
    #pragma unroll
    for (int r = 0; r < ROWS; ++r) s[r] = facc[r].x + facc[r].y;

    #pragma unroll
    for (int off = 16; off > 0; off >>= 1) {
        #pragma unroll
        for (int r = 0; r < ROWS; ++r)
            s[r] += __shfl_xor_sync(0xFFFFFFFFu, s[r], off);
    }

    if (lane == 0) {
        #pragma unroll
        for (int r = 0; r < ROWS; ++r) {
            if (mode == MODE_FP32)
                reinterpret_cast<float*>(outptr)[n0 + r] = s[r];
            else if (mode == MODE_BF16)
                reinterpret_cast<__nv_bfloat16*>(outptr)[n0 + r] = __float2bfloat16(s[r]);
            else
                reinterpret_cast<__half*>(outptr)[n0 + r] = __float2half(s[r]);
        }
    }
}

extern "C" void kernel_launch(void* const* d_in, const int* in_sizes, int n_in,
                              void* d_out, int out_size)
{
    // Identify tensors by element count (ordering-proof):
    //   A = 8192, B = N*K/2 (largest), SZ = N*K/32*2
    int iA = -1, iB = -1, iS = -1;
    for (int i = 0; i < n_in; ++i) {
        if      (in_sizes[i] == K_DIM) iA = i;
        else if (iB < 0 || in_sizes[i] > in_sizes[iB]) { if (iB >= 0) iS = iB; iB = i; }
        else iS = i;
    }
    if (iA < 0 || iB < 0 || iS < 0) { iA = 0; iB = 1; iS = 2; }

    const void* A  = d_in[iA];
    const int*  B  = (const int*)d_in[iB];
    const void* SZ = d_in[iS];

    const int N = in_sizes[iB] / KH;

    probe_kernel<<<1, THREADS>>>((const uint32_t*)A);

    const int rows_per_block = WARPS * ROWS;
    const int grid = (N + rows_per_block - 1) / rows_per_block;
    gemv_int4_kernel<<<grid, THREADS>>>(A, B, SZ, d_out, N);
}

// round 15
// speedup vs baseline: 1.3513x; 1.0791x over previous
#include <cuda_runtime.h>
#include <cuda_fp16.h>
#include <cuda_bf16.h>
#include <cstdint>

// int4 weight-only quantized GEMV on GB300.
// Logical: A [1, K=8192], B int32 [N, K/2] (one byte per int32, two nibbles,
// low nibble = even k), scalesAndZeros [N, K/32, 2], out [1, N].
// The harness transports fp16 tensors as float32 (exact upcast, low 13
// mantissa bits zero) — detected at runtime; fp16/bf16 fallbacks kept.

#define K_DIM   8192
#define KH      (K_DIM / 2)      // 4096 int32 words per row
#define KH4     (KH / 4)         // 1024 uint4 per row
#define NGROUP  (K_DIM / 32)     // 256 groups per row
#define WARPS   8
#define THREADS (WARPS * 32)
#define ROWS    4                // N-rows per warp
#define STAGES  (KH4 / 128)      // 8 stages: warp eats 128 uint4/row/stage

#define MODE_FP16 0
#define MODE_FP32 1
#define MODE_BF16 2

__device__ int g_mode;

// Dtype probe over the first 4096 32-bit words of A.
// FP32-from-fp16 signature: low 13 mantissa bits of every word are zero.
// Genuine fp16/bf16 data (two values/word) has random bits 0-12.
// fp16 vs bf16 fallback: max |halfword as fp16| (fp16 N(0,1) max ~4.1;
// bf16 bits as fp16 bounded ~2.3; threshold 3.0 = 0x4200).
__global__ void probe_kernel(const uint32_t* __restrict__ A)
{
    __shared__ int lo13_nonzero;
    __shared__ int maxmag;
    if (threadIdx.x == 0) { lo13_nonzero = 0; maxmag = 0; }
    __syncthreads();

    int nz = 0, lmax = 0;
    for (int i = threadIdx.x; i < 4096; i += THREADS) {
        uint32_t w = A[i];
        if (w & 0x1FFFu) nz++;
        int m0 = (int)(w & 0x7FFFu);
        int m1 = (int)((w >> 16) & 0x7FFFu);
        lmax = max(lmax, max(m0, m1));
    }
    if (nz) atomicAdd(&lo13_nonzero, nz);
    atomicMax(&maxmag, lmax);
    __syncthreads();

    if (threadIdx.x == 0) {
        if (lo13_nonzero == 0)      g_mode = MODE_FP32;
        else if (maxmag > 0x4200)   g_mode = MODE_FP16;
        else                        g_mode = MODE_BF16;
    }
}

// Load one (scale, zero) pair for group g of a row, packed as (half s | half z)
// in a single 32-bit register. Lane-coalesced when g = base + lane.
template<int MODE>
__device__ __forceinline__ uint32_t load_sz_packed(const void* __restrict__ SZ,
                                                   size_t row, int g)
{
    if (MODE == MODE_FP32) {
        float2 f = __ldcs(&reinterpret_cast<const float2*>(SZ)[row * NGROUP + g]);
        half2 h = __floats2half2_rn(f.x, f.y);   // exact for fp16-origin data
        return *reinterpret_cast<uint32_t*>(&h);
    } else if (MODE == MODE_BF16) {
        uint32_t w = __ldcs(&reinterpret_cast<const uint32_t*>(SZ)[row * NGROUP + g]);
        uint32_t lo = w << 16, hi = w & 0xFFFF0000u;
        half2 h = __floats2half2_rn(__uint_as_float(lo), __uint_as_float(hi));
        return *reinterpret_cast<uint32_t*>(&h);
    } else {
        return __ldcs(&reinterpret_cast<const uint32_t*>(SZ)[row * NGROUP + g]);
    }
}

// 4 half2 dequant+dot chain for one uint4 (8 weights), flushed to fp32.
__device__ __forceinline__ void dot_u4(uint4 bv, uint4 av, half2 s2, half2 z2,
                                       half2 c1032, float2& facc)
{
    uint32_t v, hb; half2 h2, d2, w2, a2, acc2;

    v = (uint32_t)bv.x;
    hb = ((v & 0xFu) | 0x64006400u) | ((v << 12) & 0x000F0000u);
    h2 = *reinterpret_cast<half2*>(&hb);
    d2 = __hsub2(h2, c1032);                 // exact (q - 8), Sterbenz
    w2 = __hfma2(d2, s2, z2);
    a2 = *reinterpret_cast<half2*>(&av.x);
    acc2 = __hmul2(a2, w2);

    v = (uint32_t)bv.y;
    hb = ((v & 0xFu) | 0x64006400u) | ((v << 12) & 0x000F0000u);
    h2 = *reinterpret_cast<half2*>(&hb);
    d2 = __hsub2(h2, c1032);
    w2 = __hfma2(d2, s2, z2);
    a2 = *reinterpret_cast<half2*>(&av.y);
    acc2 = __hfma2(a2, w2, acc2);

    v = (uint32_t)bv.z;
    hb = ((v & 0xFu) | 0x64006400u) | ((v << 12) & 0x000F0000u);
    h2 = *reinterpret_cast<half2*>(&hb);
    d2 = __hsub2(h2, c1032);
    w2 = __hfma2(d2, s2, z2);
    a2 = *reinterpret_cast<half2*>(&av.z);
    acc2 = __hfma2(a2, w2, acc2);

    v = (uint32_t)bv.w;
    hb = ((v & 0xFu) | 0x64006400u) | ((v << 12) & 0x000F0000u);
    h2 = *reinterpret_cast<half2*>(&hb);
    d2 = __hsub2(h2, c1032);
    w2 = __hfma2(d2, s2, z2);
    a2 = *reinterpret_cast<half2*>(&av.w);
    acc2 = __hfma2(a2, w2, acc2);

    float2 f = __half22float2(acc2);
    facc.x += f.x;
    facc.y += f.y;
}

// Coalesced front-batched mainloop. Per stage, per row: 4 fully-coalesced
// LDG.128 (lane reads uint4 index stage*128 + j*32 + lane -> 512 contiguous
// bytes per warp-LDG = 4 cache lines = minimum wavefronts) plus ONE coalesced
// packed-scale LDG covering the 32 groups of the stage; per-j scales are
// fetched by warp shuffle (source lane = j*8 + lane/4).
template<int MODE>
__device__ __forceinline__ void mainloop(const uint4* __restrict__ Br[ROWS],
                                         const void* __restrict__ SZ, size_t n0,
                                         const uint4* __restrict__ As4, int lane,
                                         float2* facc)
{
    const half2 c1032 = __half2half2(__ushort_as_half(0x6408));  // 1032.0

    #pragma unroll
    for (int sup = 0; sup < STAGES; ++sup) {
        const int base = sup * 128 + lane;

        uint4    bv[ROWS][4];
        uint32_t psz[ROWS];

        // ---- issue all loads first (16 coalesced LDG.128 + 4 LDG scale) ----
        #pragma unroll
        for (int r = 0; r < ROWS; ++r) {
            #pragma unroll
            for (int j = 0; j < 4; ++j)
                bv[r][j] = __ldcs(&Br[r][base + j * 32]);
        }
        #pragma unroll
        for (int r = 0; r < ROWS; ++r)
            psz[r] = load_sz_packed<MODE>(SZ, n0 + r, sup * 32 + lane);

        // ---- compute: one smem av read serves all 4 rows ----
        #pragma unroll
        for (int j = 0; j < 4; ++j) {
            uint4 av = As4[base + j * 32];        // LDS.128, conflict-free
            const int src = j * 8 + (lane >> 2);  // group owner lane
            #pragma unroll
            for (int r = 0; r < ROWS; ++r) {
                uint32_t p = __shfl_sync(0xFFFFFFFFu, psz[r], src);
                half2 szh = *reinterpret_cast<half2*>(&p);
                half2 s2 = __half2half2(__low2half(szh));
                half2 z2 = __half2half2(__high2half(szh));
                dot_u4(bv[r][j], av, s2, z2, c1032, facc[r]);
            }
        }
    }
}

__global__ __launch_bounds__(THREADS, 2)
void gemv_int4_kernel(const void* __restrict__ Aptr,
                      const int*  __restrict__ B,
                      const void* __restrict__ SZptr,
                      void*       __restrict__ outptr,
                      int N)
{
    const int mode = g_mode;

    // A staged as 4096 packed half2 pairs; plain layout (coalesced mainloop
    // reads are naturally conflict-free).
    __shared__ __align__(16) uint32_t a_sm[KH];

    if (mode == MODE_FP32) {
        const float2* Av = reinterpret_cast<const float2*>(Aptr);
        for (int i = threadIdx.x; i < KH; i += THREADS) {
            float2 v = Av[i];
            half2 h = __floats2half2_rn(v.x, v.y);
            a_sm[i] = *reinterpret_cast<uint32_t*>(&h);
        }
    } else if (mode == MODE_BF16) {
        const uint32_t* Av = reinterpret_cast<const uint32_t*>(Aptr);
        for (int i = threadIdx.x; i < KH; i += THREADS) {
            uint32_t w = Av[i];
            uint32_t lo = w << 16, hi = w & 0xFFFF0000u;   // bf16 -> fp32 shift
            half2 h = __floats2half2_rn(__uint_as_float(lo), __uint_as_float(hi));
            a_sm[i] = *reinterpret_cast<uint32_t*>(&h);
        }
    } else { // MODE_FP16
        const uint32_t* Av = reinterpret_cast<const uint32_t*>(Aptr);
        for (int i = threadIdx.x; i < KH; i += THREADS)
            a_sm[i] = Av[i];
    }
    __syncthreads();

    const int warp = threadIdx.x >> 5;
    const int lane = threadIdx.x & 31;
    const int n0 = (blockIdx.x * WARPS + warp) * ROWS;
    if (n0 >= N) return;

    const uint4* Br[ROWS];
    #pragma unroll
    for (int r = 0; r < ROWS; ++r)
        Br[r] = reinterpret_cast<const uint4*>(B + (size_t)(n0 + r) * KH);
    const uint4* As4 = reinterpret_cast<const uint4*>(a_sm);

    float2 facc[ROWS];
    #pragma unroll
    for (int r = 0; r < ROWS; ++r) facc[r] = make_float2(0.f, 0.f);

    if (mode == MODE_FP32)
        mainloop<MODE_FP32>(Br, SZptr, (size_t)n0, As4, lane, facc);
    else if (mode == MODE_BF16)
        mainloop<MODE_BF16>(Br, SZptr, (size_t)n0, As4, lane, facc);
    else
        mainloop<MODE_FP16>(Br, SZptr, (size_t)n0, As4, lane, facc);

    float s[ROWS];
    #pragma unroll
    for (int r = 0; r < ROWS; ++r) s[r] = facc[r].x + facc[r].y;

    #pragma unroll
    for (int off = 16; off > 0; off >>= 1) {
        #pragma unroll
        for (int r = 0; r < ROWS; ++r)
            s[r] += __shfl_xor_sync(0xFFFFFFFFu, s[r], off);
    }

    if (lane == 0) {
        #pragma unroll
        for (int r = 0; r < ROWS; ++r) {
            if (mode == MODE_FP32)
                reinterpret_cast<float*>(outptr)[n0 + r] = s[r];
            else if (mode == MODE_BF16)
                reinterpret_cast<__nv_bfloat16*>(outptr)[n0 + r] = __float2bfloat16(s[r]);
            else
                reinterpret_cast<__half*>(outptr)[n0 + r] = __float2half(s[r]);
        }
    }
}

extern "C" void kernel_launch(void* const* d_in, const int* in_sizes, int n_in,
                              void* d_out, int out_size)
{
    // Identify tensors by element count (ordering-proof):
    //   A = 8192, B = N*K/2 (largest), SZ = N*K/32*2
    int iA = -1, iB = -1, iS = -1;
    for (int i = 0; i < n_in; ++i) {
        if      (in_sizes[i] == K_DIM) iA = i;
        else if (iB < 0 || in_sizes[i] > in_sizes[iB]) { if (iB >= 0) iS = iB; iB = i; }
        else iS = i;
    }
    if (iA < 0 || iB < 0 || iS < 0) { iA = 0; iB = 1; iS = 2; }

    const void* A  = d_in[iA];
    const int*  B  = (const int*)d_in[iB];
    const void* SZ = d_in[iS];

    const int N = in_sizes[iB] / KH;

    probe_kernel<<<1, THREADS>>>((const uint32_t*)A);

    const int rows_per_block = WARPS * ROWS;
    const int grid = (N + rows_per_block - 1) / rows_per_block;
    gemv_int4_kernel<<<grid, THREADS>>>(A, B, SZ, d_out, N);
}